// round 15
// baseline (speedup 1.0000x reference)
#include <cuda_runtime.h>
#include <cuda_fp16.h>
#include <cstdint>
#include <cstddef>

#define B_   8
#define C_   192
#define HW_  16384
#define D_   64

typedef unsigned long long u64;
typedef unsigned int u32;

__device__ __half g_G[(size_t)B_ * HW_ * 192];     // gate pre-activations, fp16 (50MB, L2-resident)
__device__ float  g_Hs[2][(size_t)B_ * HW_ * D_];  // per-axis hidden sum (fwd+bwd)
__device__ float  g_Wc[C_ * 192];                  // folded input weights [c][g]
__device__ float  g_bc[192];
__device__ float  g_Wot[D_ * C_];                  // Wo^T [d][c]

__device__ __forceinline__ void fma2(u64 &acc, u64 a, u64 b) {
    asm("fma.rn.f32x2 %0, %1, %2, %0;" : "+l"(acc) : "l"(a), "l"(b));
}
__device__ __forceinline__ u64 pack2(float x, float y) {
    u64 r; asm("mov.b64 %0, {%1, %2};" : "=l"(r) : "f"(x), "f"(y)); return r;
}
__device__ __forceinline__ float2 unpack2(u64 v) {
    float2 r; asm("mov.b64 {%0, %1}, %2;" : "=f"(r.x), "=f"(r.y) : "l"(v)); return r;
}
__device__ __forceinline__ float sigm(float x) {
    float e; asm("ex2.approx.f32 %0, %1;" : "=f"(e) : "f"(-1.442695041f * x));
    float r; asm("rcp.approx.f32 %0, %1;" : "=f"(r) : "f"(1.f + e));
    return r;
}
__device__ __forceinline__ float tanhx(float x) {
    float r; asm("tanh.approx.f32 %0, %1;" : "=f"(r) : "f"(x)); return r;
}
__device__ __forceinline__ u32 h2u(__half2 h) { return *reinterpret_cast<u32*>(&h); }

// ---------------- kernel 1: fold weights ----------------
__global__ void prep_kernel(const float* __restrict__ Wi, const float* __restrict__ bi,
                            const float* __restrict__ Wih, const float* __restrict__ bih,
                            const float* __restrict__ Wo) {
    const int bid = blockIdx.x;
    const int c = threadIdx.x;
    if (bid < 192) {
        const int g = bid;
        float acc = 0.f;
        #pragma unroll 8
        for (int d = 0; d < 64; d++) acc += Wih[g * 64 + d] * Wi[d * 192 + c];
        g_Wc[c * 192 + g] = acc;
        if (c == 0) {
            float s = bih[g];
            for (int d = 0; d < 64; d++) s += Wih[g * 64 + d] * bi[d];
            g_bc[g] = s;
        }
    } else {
        const int d = bid - 192;
        g_Wot[d * 192 + c] = Wo[c * 64 + d];
    }
}

// ---------------- kernel 2: G = Wc @ x + bc  (f32x2, double-buffered K-chunks) ----------------
// block: 256 px x 64 g, K=192 in 12 chunks of 16, smem double-buffered (48KB).
// Per chunk: prefetch next chunk's LDGs into regs BEFORE computing current,
// STS into the idle buffer, ONE barrier. Global latency hidden under 16cc of fma2.
__global__ void __launch_bounds__(256) g_gemm_kernel(const float* __restrict__ x, const int yoff) {
    const int pblk = blockIdx.y + yoff;   // 0..511
    const int b  = pblk >> 6;
    const int p0 = (pblk & 63) * 256;
    const int g0 = blockIdx.x * 64;
    const int tid = threadIdx.x;
    const int tx = tid & 31;
    const int ty = tid >> 5;

    __shared__ __align__(16) float  sX[2][16][256];   // 32KB
    __shared__ __align__(16) float2 sWd[2][16][64];   // 16KB

    u64 acc[2][2][8];
    #pragma unroll
    for (int h = 0; h < 2; h++)
        #pragma unroll
        for (int p = 0; p < 2; p++)
            #pragma unroll
            for (int j = 0; j < 8; j++) acc[h][p][j] = 0ULL;

    const float* xb = x + (size_t)b * C_ * HW_ + p0;

    // staging registers
    float4 rx[4];
    float  rw[4];
    const int xcc[4] = { (tid + 0) >> 6, (tid + 256) >> 6, (tid + 512) >> 6, (tid + 768) >> 6 };
    const int xq4 = (tid & 63) * 4;
    const int wgg = tid & 63;

    // prefetch chunk 0
    #pragma unroll
    for (int i = 0; i < 4; i++)
        rx[i] = *(const float4*)(xb + (size_t)xcc[i] * HW_ + xq4);
    #pragma unroll
    for (int i = 0; i < 4; i++)
        rw[i] = g_Wc[(xcc[i]) * 192 + g0 + wgg];     // same cc pattern (16 cc x 64 g / 256 thr = 4)
    #pragma unroll
    for (int i = 0; i < 4; i++) {
        ((float4*)sX[0][xcc[i]])[tid & 63] = rx[i];
        sWd[0][xcc[i]][wgg] = make_float2(rw[i], rw[i]);
    }
    __syncthreads();

    for (int k = 0; k < 12; k++) {
        const int cur = k & 1, nxt = cur ^ 1;
        const int cbase = (k + 1) * 16;

        // ---- prefetch chunk k+1 into regs (overlaps the compute below) ----
        if (k < 11) {
            #pragma unroll
            for (int i = 0; i < 4; i++)
                rx[i] = *(const float4*)(xb + (size_t)(cbase + xcc[i]) * HW_ + xq4);
            #pragma unroll
            for (int i = 0; i < 4; i++)
                rw[i] = g_Wc[(cbase + xcc[i]) * 192 + g0 + wgg];
        }

        // ---- compute on buffer cur ----
        #pragma unroll
        for (int cc = 0; cc < 16; cc++) {
            longlong2 xA = *(const longlong2*)&sX[cur][cc][4 * tx];
            longlong2 xB = *(const longlong2*)&sX[cur][cc][128 + 4 * tx];
            const longlong2* wp = (const longlong2*)&sWd[cur][cc][8 * ty];
            longlong2 w01 = wp[0], w23 = wp[1], w45 = wp[2], w67 = wp[3];
            u64 wd[8] = { (u64)w01.x, (u64)w01.y, (u64)w23.x, (u64)w23.y,
                          (u64)w45.x, (u64)w45.y, (u64)w67.x, (u64)w67.y };
            #pragma unroll
            for (int j = 0; j < 8; j++) {
                fma2(acc[0][0][j], wd[j], (u64)xA.x);
                fma2(acc[0][1][j], wd[j], (u64)xA.y);
                fma2(acc[1][0][j], wd[j], (u64)xB.x);
                fma2(acc[1][1][j], wd[j], (u64)xB.y);
            }
        }

        // ---- stage chunk k+1 into the idle buffer (nobody reads nxt this iter) ----
        if (k < 11) {
            #pragma unroll
            for (int i = 0; i < 4; i++) {
                ((float4*)sX[nxt][xcc[i]])[tid & 63] = rx[i];
                sWd[nxt][xcc[i]][wgg] = make_float2(rw[i], rw[i]);
            }
        }
        __syncthreads();
    }

    float bc[8];
    *(float4*)&bc[0] = *(const float4*)&g_bc[g0 + 8 * ty];
    *(float4*)&bc[4] = *(const float4*)&g_bc[g0 + 8 * ty + 4];

    #pragma unroll
    for (int h = 0; h < 2; h++) {
        #pragma unroll
        for (int p = 0; p < 2; p++) {
            const size_t q = (size_t)b * HW_ + p0 + h * 128 + 4 * tx + 2 * p;
            float2 v[8];
            #pragma unroll
            for (int j = 0; j < 8; j++) v[j] = unpack2(acc[h][p][j]);
            uint4 s0, s1;
            s0.x = h2u(__floats2half2_rn(v[0].x + bc[0], v[1].x + bc[1]));
            s0.y = h2u(__floats2half2_rn(v[2].x + bc[2], v[3].x + bc[3]));
            s0.z = h2u(__floats2half2_rn(v[4].x + bc[4], v[5].x + bc[5]));
            s0.w = h2u(__floats2half2_rn(v[6].x + bc[6], v[7].x + bc[7]));
            s1.x = h2u(__floats2half2_rn(v[0].y + bc[0], v[1].y + bc[1]));
            s1.y = h2u(__floats2half2_rn(v[2].y + bc[2], v[3].y + bc[3]));
            s1.z = h2u(__floats2half2_rn(v[4].y + bc[4], v[5].y + bc[5]));
            s1.w = h2u(__floats2half2_rn(v[6].y + bc[6], v[7].y + bc[7]));
            *(uint4*)(&g_G[q * 192 + g0 + 8 * ty])       = s0;
            *(uint4*)(&g_G[(q + 1) * 192 + g0 + 8 * ty]) = s1;
        }
    }
}

// ---------------- kernel 3: GRU scan — R11 version (measured best), untouched ----------------
__global__ void __launch_bounds__(192, 4) scan_kernel(const float* __restrict__ Whh,
                                                      const float* __restrict__ bhh) {
    __shared__ __align__(16) float h2[2][2][64];
    __shared__ float hg[2][192];
    __shared__ float buf[128 * 64];

    const int blk  = blockIdx.x;
    const int axis = blk >> 10;
    const int ll   = blk & 1023;
    const int b    = ll >> 7;
    const int line = ll & 127;
    const int g    = threadIdx.x;

    u64 w2[32];
    {
        const float2* wr = (const float2*)(Whh + g * 64);
        #pragma unroll
        for (int k = 0; k < 32; k++) { float2 w = wr[k]; w2[k] = pack2(w.x, w.y); }
    }
    const float bh = bhh[g];

    for (int i = g; i < 256; i += 192) ((float*)h2)[i] = 0.f;
    __syncthreads();

    const __half* Gb = g_G + (size_t)b * HW_ * 192;
    float* outS = g_Hs[axis] + (size_t)b * HW_ * 64;

    const bool gate_on = (g < 128);
    const int s_it = g >> 6;
    const int d_it = g & 63;
    const int pm   = axis ? 128 : 1;
    const int pa   = axis ? line : line * 128;

    float cx = 0.f, cz = 0.f, cn = 0.f;
    if (gate_on) {
        const int tt = s_it ? 127 : 0;
        const __half* Gp = Gb + (size_t)(pa + tt * pm) * 192 + d_it;
        cx = __half2float(__ldg(Gp));
        cz = __half2float(__ldg(Gp + 64));
        cn = __half2float(__ldg(Gp + 128));
    }

    for (int t = 0; t < 128; t++) {
        const int cur = (t & 1);
        const int nxt = cur ^ 1;

        float nx = 0.f, nz = 0.f, nn = 0.f;
        if (gate_on) {
            const int tq = (t + 1) & 127;
            const int tt = s_it ? 127 - tq : tq;
            const __half* Gp = Gb + (size_t)(pa + tt * pm) * 192 + d_it;
            nx = __half2float(__ldg(Gp));
            nz = __half2float(__ldg(Gp + 64));
            nn = __half2float(__ldg(Gp + 128));
        }

        u64 a0 = 0ULL, a1 = 0ULL;
        {
            const longlong2* p0 = (const longlong2*)h2[cur][0];
            const longlong2* p1 = (const longlong2*)h2[cur][1];
            #pragma unroll
            for (int kk = 0; kk < 16; kk++) {
                longlong2 q0 = p0[kk], q1 = p1[kk];
                const u64 wA = w2[2 * kk], wB = w2[2 * kk + 1];
                fma2(a0, wA, (u64)q0.x); fma2(a1, wA, (u64)q1.x);
                fma2(a0, wB, (u64)q0.y); fma2(a1, wB, (u64)q1.y);
            }
        }
        {
            float2 f0 = unpack2(a0), f1 = unpack2(a1);
            hg[0][g] = bh + f0.x + f0.y;
            hg[1][g] = bh + f1.x + f1.y;
        }
        __syncthreads();

        if (gate_on) {
            const float rr = sigm(cx + hg[s_it][d_it]);
            const float zz = sigm(cz + hg[s_it][64 + d_it]);
            const float pre = cn + rr * hg[s_it][128 + d_it];
            const float nv = tanhx(pre);
            const float hold = h2[cur][s_it][d_it];
            const float hnew = (1.f - zz) * nv + zz * hold;
            h2[nxt][s_it][d_it] = hnew;
            const int tt = s_it ? 127 - t : t;
            float* o = buf + tt * 64 + d_it;
            if (t < 64) *o = hnew;
            else        *o = *o + hnew;
        }
        __syncthreads();

        cx = nx; cz = nz; cn = nn;
    }

    for (int i = g; i < 128 * 64; i += 192) {
        const int tt = i >> 6;
        const int d = i & 63;
        const int p = axis ? (tt * 128 + line) : (line * 128 + tt);
        outS[(size_t)p * 64 + d] = buf[i];
    }
}

// ---------------- kernel 4: out = Wo @ avg(h) + bo  (v3, measured best) ----------------
#define SH_STRIDE 132
__global__ void __launch_bounds__(256) out_gemm_kernel(const float* __restrict__ bo,
                                                       float* __restrict__ out) {
    extern __shared__ __align__(16) char osm[];
    float*  sH  = (float*)osm;                            // [64][SH_STRIDE]
    float2* sWd = (float2*)(osm + 64 * SH_STRIDE * 4);    // [64][64]

    const int bx = blockIdx.x;            // 0..1023
    const int b  = bx >> 7;
    const int p0 = (bx & 127) * 128;
    const int c0 = blockIdx.y * 64;
    const int tid = threadIdx.x;
    const int tx = tid & 31;
    const int ty = tid >> 5;

    const size_t base = ((size_t)b * HW_ + p0) * 64;
    const float* hH = g_Hs[0] + base;
    const float* hV = g_Hs[1] + base;

    #pragma unroll
    for (int i = 0; i < 32; i++) {
        int lin = tid + i * 256;
        int pp = lin >> 6, dd = lin & 63;
        sH[dd * SH_STRIDE + pp] = 0.25f * (hH[(size_t)pp * 64 + dd] + hV[(size_t)pp * 64 + dd]);
    }
    #pragma unroll
    for (int i = 0; i < 16; i++) {
        int lin = tid + i * 256;
        int dd = lin >> 6, cc = lin & 63;
        float w = g_Wot[dd * 192 + c0 + cc];
        sWd[dd * 64 + cc] = make_float2(w, w);
    }
    __syncthreads();

    u64 acc[8][2];
    #pragma unroll
    for (int j = 0; j < 8; j++) { acc[j][0] = 0ULL; acc[j][1] = 0ULL; }

    #pragma unroll
    for (int dd = 0; dd < 64; dd++) {
        const u64* ap = (const u64*)&sH[dd * SH_STRIDE + 4 * tx];
        u64 aLo = ap[0], aHi = ap[1];
        const longlong2* wp = (const longlong2*)&sWd[dd * 64 + 8 * ty];
        longlong2 w01 = wp[0], w23 = wp[1], w45 = wp[2], w67 = wp[3];
        u64 wd[8] = { (u64)w01.x, (u64)w01.y, (u64)w23.x, (u64)w23.y,
                      (u64)w45.x, (u64)w45.y, (u64)w67.x, (u64)w67.y };
        #pragma unroll
        for (int j = 0; j < 8; j++) {
            fma2(acc[j][0], wd[j], aLo);
            fma2(acc[j][1], wd[j], aHi);
        }
    }

    #pragma unroll
    for (int j = 0; j < 8; j++) {
        const int c = c0 + 8 * ty + j;
        const float bv = bo[c];
        float2 lo = unpack2(acc[j][0]), hi = unpack2(acc[j][1]);
        float4 v = make_float4(lo.x + bv, lo.y + bv, hi.x + bv, hi.y + bv);
        *(float4*)&out[((size_t)b * 192 + c) * HW_ + p0 + 4 * tx] = v;
    }
}

// ---------------- launch ----------------
extern "C" void kernel_launch(void* const* d_in, const int* in_sizes, int n_in,
                              void* d_out, int out_size) {
    const float* x   = (const float*)d_in[0];
    const float* Wi  = (const float*)d_in[1];
    const float* bi  = (const float*)d_in[2];
    const float* Wih = (const float*)d_in[3];
    const float* Whh = (const float*)d_in[4];
    const float* bih = (const float*)d_in[5];
    const float* bhh = (const float*)d_in[6];
    const float* Wo  = (const float*)d_in[7];
    const float* bo  = (const float*)d_in[8];
    float* out = (float*)d_out;

    const int OUT_SMEM = 64 * SH_STRIDE * 4 + 64 * 64 * 8;   // 66560 B
    cudaFuncSetAttribute(out_gemm_kernel, cudaFuncAttributeMaxDynamicSharedMemorySize, OUT_SMEM);

    prep_kernel<<<256, 192>>>(Wi, bi, Wih, bih, Wo);
    g_gemm_kernel<<<dim3(3, 256), 256>>>(x, 0);
    g_gemm_kernel<<<dim3(3, 256), 256>>>(x, 256);
    scan_kernel<<<2048, 192>>>(Whh, bhh);
    out_gemm_kernel<<<dim3(1024, 3), 256, OUT_SMEM>>>(bo, out);
}

// round 16
// speedup vs baseline: 1.0707x; 1.0707x over previous
#include <cuda_runtime.h>
#include <cuda_fp16.h>
#include <cstdint>
#include <cstddef>

#define B_   8
#define C_   192
#define HW_  16384
#define D_   64

typedef unsigned long long u64;
typedef unsigned int u32;

__device__ __half g_G[(size_t)B_ * HW_ * 192];     // gate pre-activations, fp16 (50MB, L2-resident)
__device__ float  g_Hs[2][(size_t)B_ * HW_ * D_];  // per-axis hidden sum (fwd+bwd)
__device__ float  g_Wc[C_ * 192];                  // folded input weights [c][g]
__device__ float  g_bc[192];
__device__ float  g_Wot[D_ * C_];                  // Wo^T [d][c]

__device__ __forceinline__ void fma2(u64 &acc, u64 a, u64 b) {
    asm("fma.rn.f32x2 %0, %1, %2, %0;" : "+l"(acc) : "l"(a), "l"(b));
}
__device__ __forceinline__ u64 pack2(float x, float y) {
    u64 r; asm("mov.b64 %0, {%1, %2};" : "=l"(r) : "f"(x), "f"(y)); return r;
}
__device__ __forceinline__ float2 unpack2(u64 v) {
    float2 r; asm("mov.b64 {%0, %1}, %2;" : "=f"(r.x), "=f"(r.y) : "l"(v)); return r;
}
__device__ __forceinline__ float sigm(float x) {
    float e; asm("ex2.approx.f32 %0, %1;" : "=f"(e) : "f"(-1.442695041f * x));
    float r; asm("rcp.approx.f32 %0, %1;" : "=f"(r) : "f"(1.f + e));
    return r;
}
__device__ __forceinline__ float tanhx(float x) {
    float r; asm("tanh.approx.f32 %0, %1;" : "=f"(r) : "f"(x)); return r;
}
__device__ __forceinline__ u32 h2u(__half2 h) { return *reinterpret_cast<u32*>(&h); }
__device__ __forceinline__ u32 smem_u32(const void* p) {
    u32 a; asm("{ .reg .u64 t; cvta.to.shared.u64 t, %1; cvt.u32.u64 %0, t; }" : "=r"(a) : "l"(p));
    return a;
}
__device__ __forceinline__ void cp_async16(u32 dst, const void* src) {
    asm volatile("cp.async.ca.shared.global [%0], [%1], 16;" :: "r"(dst), "l"(src));
}

// ---------------- kernel 1: fold weights ----------------
__global__ void prep_kernel(const float* __restrict__ Wi, const float* __restrict__ bi,
                            const float* __restrict__ Wih, const float* __restrict__ bih,
                            const float* __restrict__ Wo) {
    const int bid = blockIdx.x;
    const int c = threadIdx.x;
    if (bid < 192) {
        const int g = bid;
        float acc = 0.f;
        #pragma unroll 8
        for (int d = 0; d < 64; d++) acc += Wih[g * 64 + d] * Wi[d * 192 + c];
        g_Wc[c * 192 + g] = acc;
        if (c == 0) {
            float s = bih[g];
            for (int d = 0; d < 64; d++) s += Wih[g * 64 + d] * bi[d];
            g_bc[g] = s;
        }
    } else {
        const int d = bid - 192;
        g_Wot[d * 192 + c] = Wo[c * 64 + d];
    }
}

// ---------------- kernel 2: G = Wc @ x + bc  (cp.async double-buffered) ----------------
// x chunks stream via cp.async (zero staging registers); weights (4 floats) via
// registers with (w,w) duplication. One barrier per chunk; regs ~= R13 level.
__global__ void __launch_bounds__(256) g_gemm_kernel(const float* __restrict__ x, const int yoff) {
    const int pblk = blockIdx.y + yoff;   // 0..511
    const int b  = pblk >> 6;
    const int p0 = (pblk & 63) * 256;
    const int g0 = blockIdx.x * 64;
    const int tid = threadIdx.x;
    const int tx = tid & 31;
    const int ty = tid >> 5;

    __shared__ __align__(16) float  sX[2][16][256];   // 32KB
    __shared__ __align__(16) float2 sWd[2][16][64];   // 16KB  (total 48KB = static max)

    u64 acc[2][2][8];
    #pragma unroll
    for (int h = 0; h < 2; h++)
        #pragma unroll
        for (int p = 0; p < 2; p++)
            #pragma unroll
            for (int j = 0; j < 8; j++) acc[h][p][j] = 0ULL;

    const float* xb = x + (size_t)b * C_ * HW_ + p0;

    const int cc0 = tid >> 6;             // xcc[i] = cc0 + 4*i
    const int q4  = (tid & 63) * 4;
    const int wgg = tid & 63;

    // chunk 0: x via cp.async, weights via regs
    #pragma unroll
    for (int i = 0; i < 4; i++) {
        const int cc = cc0 + 4 * i;
        cp_async16(smem_u32(&sX[0][cc][q4]), xb + (size_t)cc * HW_ + q4);
    }
    asm volatile("cp.async.commit_group;");
    #pragma unroll
    for (int i = 0; i < 4; i++) {
        const int cc = cc0 + 4 * i;
        float w = g_Wc[cc * 192 + g0 + wgg];
        sWd[0][cc][wgg] = make_float2(w, w);
    }
    asm volatile("cp.async.wait_group 0;");
    __syncthreads();

    for (int k = 0; k < 12; k++) {
        const int cur = k & 1, nxt = cur ^ 1;
        const int cbase = (k + 1) * 16;

        // ---- stream chunk k+1 x into idle buffer (no regs), stage weights ----
        float rw[4];
        if (k < 11) {
            #pragma unroll
            for (int i = 0; i < 4; i++) {
                const int cc = cc0 + 4 * i;
                cp_async16(smem_u32(&sX[nxt][cc][q4]), xb + (size_t)(cbase + cc) * HW_ + q4);
            }
            asm volatile("cp.async.commit_group;");
            #pragma unroll
            for (int i = 0; i < 4; i++)
                rw[i] = g_Wc[(cbase + cc0 + 4 * i) * 192 + g0 + wgg];
        }

        // ---- compute on buffer cur ----
        #pragma unroll
        for (int cc = 0; cc < 16; cc++) {
            longlong2 xA = *(const longlong2*)&sX[cur][cc][4 * tx];
            longlong2 xB = *(const longlong2*)&sX[cur][cc][128 + 4 * tx];
            const longlong2* wp = (const longlong2*)&sWd[cur][cc][8 * ty];
            longlong2 w01 = wp[0], w23 = wp[1], w45 = wp[2], w67 = wp[3];
            u64 wd[8] = { (u64)w01.x, (u64)w01.y, (u64)w23.x, (u64)w23.y,
                          (u64)w45.x, (u64)w45.y, (u64)w67.x, (u64)w67.y };
            #pragma unroll
            for (int j = 0; j < 8; j++) {
                fma2(acc[0][0][j], wd[j], (u64)xA.x);
                fma2(acc[0][1][j], wd[j], (u64)xA.y);
                fma2(acc[1][0][j], wd[j], (u64)xB.x);
                fma2(acc[1][1][j], wd[j], (u64)xB.y);
            }
        }

        // ---- store duplicated weights, drain cp.async, barrier ----
        if (k < 11) {
            #pragma unroll
            for (int i = 0; i < 4; i++)
                sWd[nxt][cc0 + 4 * i][wgg] = make_float2(rw[i], rw[i]);
            asm volatile("cp.async.wait_group 0;");
        }
        __syncthreads();
    }

    float bc[8];
    *(float4*)&bc[0] = *(const float4*)&g_bc[g0 + 8 * ty];
    *(float4*)&bc[4] = *(const float4*)&g_bc[g0 + 8 * ty + 4];

    #pragma unroll
    for (int h = 0; h < 2; h++) {
        #pragma unroll
        for (int p = 0; p < 2; p++) {
            const size_t q = (size_t)b * HW_ + p0 + h * 128 + 4 * tx + 2 * p;
            float2 v[8];
            #pragma unroll
            for (int j = 0; j < 8; j++) v[j] = unpack2(acc[h][p][j]);
            uint4 s0, s1;
            s0.x = h2u(__floats2half2_rn(v[0].x + bc[0], v[1].x + bc[1]));
            s0.y = h2u(__floats2half2_rn(v[2].x + bc[2], v[3].x + bc[3]));
            s0.z = h2u(__floats2half2_rn(v[4].x + bc[4], v[5].x + bc[5]));
            s0.w = h2u(__floats2half2_rn(v[6].x + bc[6], v[7].x + bc[7]));
            s1.x = h2u(__floats2half2_rn(v[0].y + bc[0], v[1].y + bc[1]));
            s1.y = h2u(__floats2half2_rn(v[2].y + bc[2], v[3].y + bc[3]));
            s1.z = h2u(__floats2half2_rn(v[4].y + bc[4], v[5].y + bc[5]));
            s1.w = h2u(__floats2half2_rn(v[6].y + bc[6], v[7].y + bc[7]));
            *(uint4*)(&g_G[q * 192 + g0 + 8 * ty])       = s0;
            *(uint4*)(&g_G[(q + 1) * 192 + g0 + 8 * ty]) = s1;
        }
    }
}

// ---------------- kernel 3: GRU scan — R11 + split accumulator chains (16-deep) ----------------
__global__ void __launch_bounds__(192, 4) scan_kernel(const float* __restrict__ Whh,
                                                      const float* __restrict__ bhh) {
    __shared__ __align__(16) float h2[2][2][64];
    __shared__ float hg[2][192];
    __shared__ float buf[128 * 64];

    const int blk  = blockIdx.x;
    const int axis = blk >> 10;
    const int ll   = blk & 1023;
    const int b    = ll >> 7;
    const int line = ll & 127;
    const int g    = threadIdx.x;

    u64 w2[32];
    {
        const float2* wr = (const float2*)(Whh + g * 64);
        #pragma unroll
        for (int k = 0; k < 32; k++) { float2 w = wr[k]; w2[k] = pack2(w.x, w.y); }
    }
    const float bh = bhh[g];

    for (int i = g; i < 256; i += 192) ((float*)h2)[i] = 0.f;
    __syncthreads();

    const __half* Gb = g_G + (size_t)b * HW_ * 192;
    float* outS = g_Hs[axis] + (size_t)b * HW_ * 64;

    const bool gate_on = (g < 128);
    const int s_it = g >> 6;
    const int d_it = g & 63;
    const int pm   = axis ? 128 : 1;
    const int pa   = axis ? line : line * 128;

    float cx = 0.f, cz = 0.f, cn = 0.f;
    if (gate_on) {
        const int tt = s_it ? 127 : 0;
        const __half* Gp = Gb + (size_t)(pa + tt * pm) * 192 + d_it;
        cx = __half2float(__ldg(Gp));
        cz = __half2float(__ldg(Gp + 64));
        cn = __half2float(__ldg(Gp + 128));
    }

    for (int t = 0; t < 128; t++) {
        const int cur = (t & 1);
        const int nxt = cur ^ 1;

        float nx = 0.f, nz = 0.f, nn = 0.f;
        if (gate_on) {
            const int tq = (t + 1) & 127;
            const int tt = s_it ? 127 - tq : tq;
            const __half* Gp = Gb + (size_t)(pa + tt * pm) * 192 + d_it;
            nx = __half2float(__ldg(Gp));
            nz = __half2float(__ldg(Gp + 64));
            nn = __half2float(__ldg(Gp + 128));
        }

        // 4 independent 16-deep chains (a*, c*) -> halved dependency latency
        u64 a0 = 0ULL, a1 = 0ULL, c0 = 0ULL, c1 = 0ULL;
        {
            const longlong2* p0 = (const longlong2*)h2[cur][0];
            const longlong2* p1 = (const longlong2*)h2[cur][1];
            #pragma unroll
            for (int kk = 0; kk < 16; kk += 2) {
                longlong2 q0 = p0[kk], q1 = p1[kk];
                longlong2 r0 = p0[kk + 1], r1 = p1[kk + 1];
                const u64 wA = w2[2 * kk],     wB = w2[2 * kk + 1];
                const u64 wC = w2[2 * kk + 2], wD = w2[2 * kk + 3];
                fma2(a0, wA, (u64)q0.x); fma2(a1, wA, (u64)q1.x);
                fma2(a0, wB, (u64)q0.y); fma2(a1, wB, (u64)q1.y);
                fma2(c0, wC, (u64)r0.x); fma2(c1, wC, (u64)r1.x);
                fma2(c0, wD, (u64)r0.y); fma2(c1, wD, (u64)r1.y);
            }
        }
        {
            float2 f0 = unpack2(a0), f1 = unpack2(a1);
            float2 e0 = unpack2(c0), e1 = unpack2(c1);
            hg[0][g] = bh + (f0.x + f0.y) + (e0.x + e0.y);
            hg[1][g] = bh + (f1.x + f1.y) + (e1.x + e1.y);
        }
        __syncthreads();

        if (gate_on) {
            const float rr = sigm(cx + hg[s_it][d_it]);
            const float zz = sigm(cz + hg[s_it][64 + d_it]);
            const float pre = cn + rr * hg[s_it][128 + d_it];
            const float nv = tanhx(pre);
            const float hold = h2[cur][s_it][d_it];
            const float hnew = (1.f - zz) * nv + zz * hold;
            h2[nxt][s_it][d_it] = hnew;
            const int tt = s_it ? 127 - t : t;
            float* o = buf + tt * 64 + d_it;
            if (t < 64) *o = hnew;
            else        *o = *o + hnew;
        }
        __syncthreads();

        cx = nx; cz = nz; cn = nn;
    }

    for (int i = g; i < 128 * 64; i += 192) {
        const int tt = i >> 6;
        const int d = i & 63;
        const int p = axis ? (tt * 128 + line) : (line * 128 + tt);
        outS[(size_t)p * 64 + d] = buf[i];
    }
}

// ---------------- kernel 4: out = Wo @ avg(h) + bo  (v3, measured best) ----------------
#define SH_STRIDE 132
__global__ void __launch_bounds__(256) out_gemm_kernel(const float* __restrict__ bo,
                                                       float* __restrict__ out) {
    extern __shared__ __align__(16) char osm[];
    float*  sH  = (float*)osm;                            // [64][SH_STRIDE]
    float2* sWd = (float2*)(osm + 64 * SH_STRIDE * 4);    // [64][64]

    const int bx = blockIdx.x;            // 0..1023
    const int b  = bx >> 7;
    const int p0 = (bx & 127) * 128;
    const int c0 = blockIdx.y * 64;
    const int tid = threadIdx.x;
    const int tx = tid & 31;
    const int ty = tid >> 5;

    const size_t base = ((size_t)b * HW_ + p0) * 64;
    const float* hH = g_Hs[0] + base;
    const float* hV = g_Hs[1] + base;

    #pragma unroll
    for (int i = 0; i < 32; i++) {
        int lin = tid + i * 256;
        int pp = lin >> 6, dd = lin & 63;
        sH[dd * SH_STRIDE + pp] = 0.25f * (hH[(size_t)pp * 64 + dd] + hV[(size_t)pp * 64 + dd]);
    }
    #pragma unroll
    for (int i = 0; i < 16; i++) {
        int lin = tid + i * 256;
        int dd = lin >> 6, cc = lin & 63;
        float w = g_Wot[dd * 192 + c0 + cc];
        sWd[dd * 64 + cc] = make_float2(w, w);
    }
    __syncthreads();

    u64 acc[8][2];
    #pragma unroll
    for (int j = 0; j < 8; j++) { acc[j][0] = 0ULL; acc[j][1] = 0ULL; }

    #pragma unroll
    for (int dd = 0; dd < 64; dd++) {
        const u64* ap = (const u64*)&sH[dd * SH_STRIDE + 4 * tx];
        u64 aLo = ap[0], aHi = ap[1];
        const longlong2* wp = (const longlong2*)&sWd[dd * 64 + 8 * ty];
        longlong2 w01 = wp[0], w23 = wp[1], w45 = wp[2], w67 = wp[3];
        u64 wd[8] = { (u64)w01.x, (u64)w01.y, (u64)w23.x, (u64)w23.y,
                      (u64)w45.x, (u64)w45.y, (u64)w67.x, (u64)w67.y };
        #pragma unroll
        for (int j = 0; j < 8; j++) {
            fma2(acc[j][0], wd[j], aLo);
            fma2(acc[j][1], wd[j], aHi);
        }
    }

    #pragma unroll
    for (int j = 0; j < 8; j++) {
        const int c = c0 + 8 * ty + j;
        const float bv = bo[c];
        float2 lo = unpack2(acc[j][0]), hi = unpack2(acc[j][1]);
        float4 v = make_float4(lo.x + bv, lo.y + bv, hi.x + bv, hi.y + bv);
        *(float4*)&out[((size_t)b * 192 + c) * HW_ + p0 + 4 * tx] = v;
    }
}

// ---------------- launch ----------------
extern "C" void kernel_launch(void* const* d_in, const int* in_sizes, int n_in,
                              void* d_out, int out_size) {
    const float* x   = (const float*)d_in[0];
    const float* Wi  = (const float*)d_in[1];
    const float* bi  = (const float*)d_in[2];
    const float* Wih = (const float*)d_in[3];
    const float* Whh = (const float*)d_in[4];
    const float* bih = (const float*)d_in[5];
    const float* bhh = (const float*)d_in[6];
    const float* Wo  = (const float*)d_in[7];
    const float* bo  = (const float*)d_in[8];
    float* out = (float*)d_out;

    const int OUT_SMEM = 64 * SH_STRIDE * 4 + 64 * 64 * 8;   // 66560 B
    cudaFuncSetAttribute(out_gemm_kernel, cudaFuncAttributeMaxDynamicSharedMemorySize, OUT_SMEM);

    prep_kernel<<<256, 192>>>(Wi, bi, Wih, bih, Wo);
    g_gemm_kernel<<<dim3(3, 256), 256>>>(x, 0);
    g_gemm_kernel<<<dim3(3, 256), 256>>>(x, 256);
    scan_kernel<<<2048, 192>>>(Whh, bhh);
    out_gemm_kernel<<<dim3(1024, 3), 256, OUT_SMEM>>>(bo, out);
}

// round 17
// speedup vs baseline: 1.0957x; 1.0233x over previous
#include <cuda_runtime.h>
#include <cuda_fp16.h>
#include <cstdint>
#include <cstddef>

#define B_   8
#define C_   192
#define HW_  16384
#define D_   64

typedef unsigned long long u64;
typedef unsigned int u32;

__device__ __half g_G[(size_t)B_ * HW_ * 192];     // gate pre-activations, fp16 (50MB, L2-resident)
__device__ float  g_Hs[2][(size_t)B_ * HW_ * D_];  // per-axis hidden sum (fwd+bwd)
__device__ float  g_Wc[C_ * 192];                  // folded input weights [c][g]
__device__ float  g_bc[192];
__device__ float  g_Wot[D_ * C_];                  // Wo^T [d][c]

__device__ __forceinline__ void fma2(u64 &acc, u64 a, u64 b) {
    asm("fma.rn.f32x2 %0, %1, %2, %0;" : "+l"(acc) : "l"(a), "l"(b));
}
__device__ __forceinline__ u64 pack2(float x, float y) {
    u64 r; asm("mov.b64 %0, {%1, %2};" : "=l"(r) : "f"(x), "f"(y)); return r;
}
__device__ __forceinline__ float2 unpack2(u64 v) {
    float2 r; asm("mov.b64 {%0, %1}, %2;" : "=f"(r.x), "=f"(r.y) : "l"(v)); return r;
}
__device__ __forceinline__ float sigm(float x) {
    float e; asm("ex2.approx.f32 %0, %1;" : "=f"(e) : "f"(-1.442695041f * x));
    float r; asm("rcp.approx.f32 %0, %1;" : "=f"(r) : "f"(1.f + e));
    return r;
}
__device__ __forceinline__ float tanhx(float x) {
    float r; asm("tanh.approx.f32 %0, %1;" : "=f"(r) : "f"(x)); return r;
}
__device__ __forceinline__ u32 h2u(__half2 h) { return *reinterpret_cast<u32*>(&h); }
__device__ __forceinline__ u32 smem_u32(const void* p) {
    u32 a; asm("{ .reg .u64 t; cvta.to.shared.u64 t, %1; cvt.u32.u64 %0, t; }" : "=r"(a) : "l"(p));
    return a;
}
__device__ __forceinline__ void cp_async16(u32 dst, const void* src) {
    asm volatile("cp.async.ca.shared.global [%0], [%1], 16;" :: "r"(dst), "l"(src));
}

// ---------------- kernel 1: fold weights ----------------
__global__ void prep_kernel(const float* __restrict__ Wi, const float* __restrict__ bi,
                            const float* __restrict__ Wih, const float* __restrict__ bih,
                            const float* __restrict__ Wo) {
    const int bid = blockIdx.x;
    const int c = threadIdx.x;
    if (bid < 192) {
        const int g = bid;
        float acc = 0.f;
        #pragma unroll 8
        for (int d = 0; d < 64; d++) acc += Wih[g * 64 + d] * Wi[d * 192 + c];
        g_Wc[c * 192 + g] = acc;
        if (c == 0) {
            float s = bih[g];
            for (int d = 0; d < 64; d++) s += Wih[g * 64 + d] * bi[d];
            g_bc[g] = s;
        }
    } else {
        const int d = bid - 192;
        g_Wot[d * 192 + c] = Wo[c * 64 + d];
    }
}

// ---------------- kernel 2: G = Wc @ x + bc  (cp.async double-buffered, R15 WIN) ----------------
__global__ void __launch_bounds__(256) g_gemm_kernel(const float* __restrict__ x, const int yoff) {
    const int pblk = blockIdx.y + yoff;   // 0..511
    const int b  = pblk >> 6;
    const int p0 = (pblk & 63) * 256;
    const int g0 = blockIdx.x * 64;
    const int tid = threadIdx.x;
    const int tx = tid & 31;
    const int ty = tid >> 5;

    __shared__ __align__(16) float  sX[2][16][256];   // 32KB
    __shared__ __align__(16) float2 sWd[2][16][64];   // 16KB  (total 48KB)

    u64 acc[2][2][8];
    #pragma unroll
    for (int h = 0; h < 2; h++)
        #pragma unroll
        for (int p = 0; p < 2; p++)
            #pragma unroll
            for (int j = 0; j < 8; j++) acc[h][p][j] = 0ULL;

    const float* xb = x + (size_t)b * C_ * HW_ + p0;

    const int cc0 = tid >> 6;             // xcc[i] = cc0 + 4*i
    const int q4  = (tid & 63) * 4;
    const int wgg = tid & 63;

    // chunk 0: x via cp.async, weights via regs
    #pragma unroll
    for (int i = 0; i < 4; i++) {
        const int cc = cc0 + 4 * i;
        cp_async16(smem_u32(&sX[0][cc][q4]), xb + (size_t)cc * HW_ + q4);
    }
    asm volatile("cp.async.commit_group;");
    #pragma unroll
    for (int i = 0; i < 4; i++) {
        const int cc = cc0 + 4 * i;
        float w = g_Wc[cc * 192 + g0 + wgg];
        sWd[0][cc][wgg] = make_float2(w, w);
    }
    asm volatile("cp.async.wait_group 0;");
    __syncthreads();

    for (int k = 0; k < 12; k++) {
        const int cur = k & 1, nxt = cur ^ 1;
        const int cbase = (k + 1) * 16;

        float rw[4];
        if (k < 11) {
            #pragma unroll
            for (int i = 0; i < 4; i++) {
                const int cc = cc0 + 4 * i;
                cp_async16(smem_u32(&sX[nxt][cc][q4]), xb + (size_t)(cbase + cc) * HW_ + q4);
            }
            asm volatile("cp.async.commit_group;");
            #pragma unroll
            for (int i = 0; i < 4; i++)
                rw[i] = g_Wc[(cbase + cc0 + 4 * i) * 192 + g0 + wgg];
        }

        #pragma unroll
        for (int cc = 0; cc < 16; cc++) {
            longlong2 xA = *(const longlong2*)&sX[cur][cc][4 * tx];
            longlong2 xB = *(const longlong2*)&sX[cur][cc][128 + 4 * tx];
            const longlong2* wp = (const longlong2*)&sWd[cur][cc][8 * ty];
            longlong2 w01 = wp[0], w23 = wp[1], w45 = wp[2], w67 = wp[3];
            u64 wd[8] = { (u64)w01.x, (u64)w01.y, (u64)w23.x, (u64)w23.y,
                          (u64)w45.x, (u64)w45.y, (u64)w67.x, (u64)w67.y };
            #pragma unroll
            for (int j = 0; j < 8; j++) {
                fma2(acc[0][0][j], wd[j], (u64)xA.x);
                fma2(acc[0][1][j], wd[j], (u64)xA.y);
                fma2(acc[1][0][j], wd[j], (u64)xB.x);
                fma2(acc[1][1][j], wd[j], (u64)xB.y);
            }
        }

        if (k < 11) {
            #pragma unroll
            for (int i = 0; i < 4; i++)
                sWd[nxt][cc0 + 4 * i][wgg] = make_float2(rw[i], rw[i]);
            asm volatile("cp.async.wait_group 0;");
        }
        __syncthreads();
    }

    float bc[8];
    *(float4*)&bc[0] = *(const float4*)&g_bc[g0 + 8 * ty];
    *(float4*)&bc[4] = *(const float4*)&g_bc[g0 + 8 * ty + 4];

    #pragma unroll
    for (int h = 0; h < 2; h++) {
        #pragma unroll
        for (int p = 0; p < 2; p++) {
            const size_t q = (size_t)b * HW_ + p0 + h * 128 + 4 * tx + 2 * p;
            float2 v[8];
            #pragma unroll
            for (int j = 0; j < 8; j++) v[j] = unpack2(acc[h][p][j]);
            uint4 s0, s1;
            s0.x = h2u(__floats2half2_rn(v[0].x + bc[0], v[1].x + bc[1]));
            s0.y = h2u(__floats2half2_rn(v[2].x + bc[2], v[3].x + bc[3]));
            s0.z = h2u(__floats2half2_rn(v[4].x + bc[4], v[5].x + bc[5]));
            s0.w = h2u(__floats2half2_rn(v[6].x + bc[6], v[7].x + bc[7]));
            s1.x = h2u(__floats2half2_rn(v[0].y + bc[0], v[1].y + bc[1]));
            s1.y = h2u(__floats2half2_rn(v[2].y + bc[2], v[3].y + bc[3]));
            s1.z = h2u(__floats2half2_rn(v[4].y + bc[4], v[5].y + bc[5]));
            s1.w = h2u(__floats2half2_rn(v[6].y + bc[6], v[7].y + bc[7]));
            *(uint4*)(&g_G[q * 192 + g0 + 8 * ty])       = s0;
            *(uint4*)(&g_G[(q + 1) * 192 + g0 + 8 * ty]) = s1;
        }
    }
}

// ---------------- kernel 3: GRU scan — exact R13/R11 version (measured 643us best) ----------------
__global__ void __launch_bounds__(192, 4) scan_kernel(const float* __restrict__ Whh,
                                                      const float* __restrict__ bhh) {
    __shared__ __align__(16) float h2[2][2][64];
    __shared__ float hg[2][192];
    __shared__ float buf[128 * 64];

    const int blk  = blockIdx.x;
    const int axis = blk >> 10;
    const int ll   = blk & 1023;
    const int b    = ll >> 7;
    const int line = ll & 127;
    const int g    = threadIdx.x;

    u64 w2[32];
    {
        const float2* wr = (const float2*)(Whh + g * 64);
        #pragma unroll
        for (int k = 0; k < 32; k++) { float2 w = wr[k]; w2[k] = pack2(w.x, w.y); }
    }
    const float bh = bhh[g];

    for (int i = g; i < 256; i += 192) ((float*)h2)[i] = 0.f;
    __syncthreads();

    const __half* Gb = g_G + (size_t)b * HW_ * 192;
    float* outS = g_Hs[axis] + (size_t)b * HW_ * 64;

    const bool gate_on = (g < 128);
    const int s_it = g >> 6;
    const int d_it = g & 63;
    const int pm   = axis ? 128 : 1;
    const int pa   = axis ? line : line * 128;

    float cx = 0.f, cz = 0.f, cn = 0.f;
    if (gate_on) {
        const int tt = s_it ? 127 : 0;
        const __half* Gp = Gb + (size_t)(pa + tt * pm) * 192 + d_it;
        cx = __half2float(__ldg(Gp));
        cz = __half2float(__ldg(Gp + 64));
        cn = __half2float(__ldg(Gp + 128));
    }

    for (int t = 0; t < 128; t++) {
        const int cur = (t & 1);
        const int nxt = cur ^ 1;

        float nx = 0.f, nz = 0.f, nn = 0.f;
        if (gate_on) {
            const int tq = (t + 1) & 127;
            const int tt = s_it ? 127 - tq : tq;
            const __half* Gp = Gb + (size_t)(pa + tt * pm) * 192 + d_it;
            nx = __half2float(__ldg(Gp));
            nz = __half2float(__ldg(Gp + 64));
            nn = __half2float(__ldg(Gp + 128));
        }

        u64 a0 = 0ULL, a1 = 0ULL;
        {
            const longlong2* p0 = (const longlong2*)h2[cur][0];
            const longlong2* p1 = (const longlong2*)h2[cur][1];
            #pragma unroll
            for (int kk = 0; kk < 16; kk++) {
                longlong2 q0 = p0[kk], q1 = p1[kk];
                const u64 wA = w2[2 * kk], wB = w2[2 * kk + 1];
                fma2(a0, wA, (u64)q0.x); fma2(a1, wA, (u64)q1.x);
                fma2(a0, wB, (u64)q0.y); fma2(a1, wB, (u64)q1.y);
            }
        }
        {
            float2 f0 = unpack2(a0), f1 = unpack2(a1);
            hg[0][g] = bh + f0.x + f0.y;
            hg[1][g] = bh + f1.x + f1.y;
        }
        __syncthreads();

        if (gate_on) {
            const float rr = sigm(cx + hg[s_it][d_it]);
            const float zz = sigm(cz + hg[s_it][64 + d_it]);
            const float pre = cn + rr * hg[s_it][128 + d_it];
            const float nv = tanhx(pre);
            const float hold = h2[cur][s_it][d_it];
            const float hnew = (1.f - zz) * nv + zz * hold;
            h2[nxt][s_it][d_it] = hnew;
            const int tt = s_it ? 127 - t : t;
            float* o = buf + tt * 64 + d_it;
            if (t < 64) *o = hnew;
            else        *o = *o + hnew;
        }
        __syncthreads();

        cx = nx; cz = nz; cn = nn;
    }

    for (int i = g; i < 128 * 64; i += 192) {
        const int tt = i >> 6;
        const int d = i & 63;
        const int p = axis ? (tt * 128 + line) : (line * 128 + tt);
        outS[(size_t)p * 64 + d] = buf[i];
    }
}

// ---------------- kernel 4: out = Wo @ avg(h) + bo  (v3, measured best) ----------------
#define SH_STRIDE 132
__global__ void __launch_bounds__(256) out_gemm_kernel(const float* __restrict__ bo,
                                                       float* __restrict__ out) {
    extern __shared__ __align__(16) char osm[];
    float*  sH  = (float*)osm;                            // [64][SH_STRIDE]
    float2* sWd = (float2*)(osm + 64 * SH_STRIDE * 4);    // [64][64]

    const int bx = blockIdx.x;            // 0..1023
    const int b  = bx >> 7;
    const int p0 = (bx & 127) * 128;
    const int c0 = blockIdx.y * 64;
    const int tid = threadIdx.x;
    const int tx = tid & 31;
    const int ty = tid >> 5;

    const size_t base = ((size_t)b * HW_ + p0) * 64;
    const float* hH = g_Hs[0] + base;
    const float* hV = g_Hs[1] + base;

    #pragma unroll
    for (int i = 0; i < 32; i++) {
        int lin = tid + i * 256;
        int pp = lin >> 6, dd = lin & 63;
        sH[dd * SH_STRIDE + pp] = 0.25f * (hH[(size_t)pp * 64 + dd] + hV[(size_t)pp * 64 + dd]);
    }
    #pragma unroll
    for (int i = 0; i < 16; i++) {
        int lin = tid + i * 256;
        int dd = lin >> 6, cc = lin & 63;
        float w = g_Wot[dd * 192 + c0 + cc];
        sWd[dd * 64 + cc] = make_float2(w, w);
    }
    __syncthreads();

    u64 acc[8][2];
    #pragma unroll
    for (int j = 0; j < 8; j++) { acc[j][0] = 0ULL; acc[j][1] = 0ULL; }

    #pragma unroll
    for (int dd = 0; dd < 64; dd++) {
        const u64* ap = (const u64*)&sH[dd * SH_STRIDE + 4 * tx];
        u64 aLo = ap[0], aHi = ap[1];
        const longlong2* wp = (const longlong2*)&sWd[dd * 64 + 8 * ty];
        longlong2 w01 = wp[0], w23 = wp[1], w45 = wp[2], w67 = wp[3];
        u64 wd[8] = { (u64)w01.x, (u64)w01.y, (u64)w23.x, (u64)w23.y,
                      (u64)w45.x, (u64)w45.y, (u64)w67.x, (u64)w67.y };
        #pragma unroll
        for (int j = 0; j < 8; j++) {
            fma2(acc[j][0], wd[j], aLo);
            fma2(acc[j][1], wd[j], aHi);
        }
    }

    #pragma unroll
    for (int j = 0; j < 8; j++) {
        const int c = c0 + 8 * ty + j;
        const float bv = bo[c];
        float2 lo = unpack2(acc[j][0]), hi = unpack2(acc[j][1]);
        float4 v = make_float4(lo.x + bv, lo.y + bv, hi.x + bv, hi.y + bv);
        *(float4*)&out[((size_t)b * 192 + c) * HW_ + p0 + 4 * tx] = v;
    }
}

// ---------------- launch ----------------
extern "C" void kernel_launch(void* const* d_in, const int* in_sizes, int n_in,
                              void* d_out, int out_size) {
    const float* x   = (const float*)d_in[0];
    const float* Wi  = (const float*)d_in[1];
    const float* bi  = (const float*)d_in[2];
    const float* Wih = (const float*)d_in[3];
    const float* Whh = (const float*)d_in[4];
    const float* bih = (const float*)d_in[5];
    const float* bhh = (const float*)d_in[6];
    const float* Wo  = (const float*)d_in[7];
    const float* bo  = (const float*)d_in[8];
    float* out = (float*)d_out;

    const int OUT_SMEM = 64 * SH_STRIDE * 4 + 64 * 64 * 8;   // 66560 B
    cudaFuncSetAttribute(out_gemm_kernel, cudaFuncAttributeMaxDynamicSharedMemorySize, OUT_SMEM);

    prep_kernel<<<256, 192>>>(Wi, bi, Wih, bih, Wo);
    g_gemm_kernel<<<dim3(3, 256), 256>>>(x, 0);
    g_gemm_kernel<<<dim3(3, 256), 256>>>(x, 256);
    scan_kernel<<<2048, 192>>>(Whh, bhh);
    out_gemm_kernel<<<dim3(1024, 3), 256, OUT_SMEM>>>(bo, out);
}